// round 1
// baseline (speedup 1.0000x reference)
#include <cuda_runtime.h>
#include <math.h>

#define BATCH 8
#define SEQ   2048
#define EMB   1024
#define HD    64
#define NROWS (BATCH*SEQ)   // 16384

// Scratch for projections (allocation-free rule: __device__ globals)
__device__ float g_q[NROWS*HD];
__device__ float g_k[NROWS*HD];
__device__ float g_v[NROWS*HD];

// ============================================================================
// Projection: C[M,64] = X[M,1024] @ W[1024,64]; grid=(M/128, 3), block=256
// BM=128, BN=64, BK=16, per-thread 8x4 register tile.
// ============================================================================
__global__ __launch_bounds__(256) void proj_kernel(
    const float* __restrict__ x,
    const float* __restrict__ Wq,
    const float* __restrict__ Wk,
    const float* __restrict__ Wv)
{
    constexpr int BM = 128, BK = 16;
    __shared__ float Xs[BM][BK + 1];   // stride 17: conflict-free a-loads
    __shared__ float Ws[BK][HD];       // stride 64: float4 b-loads

    const float* W   = (blockIdx.y == 0) ? Wq : (blockIdx.y == 1) ? Wk : Wv;
    float*       out = (blockIdx.y == 0) ? g_q : (blockIdx.y == 1) ? g_k : g_v;

    const int m0  = blockIdx.x * BM;
    const int tid = threadIdx.x;
    const int ty  = tid >> 4;      // 0..15 -> 8 rows each
    const int tx  = tid & 15;      // 0..15 -> 4 cols each

    float acc[8][4];
#pragma unroll
    for (int i = 0; i < 8; i++)
#pragma unroll
        for (int j = 0; j < 4; j++) acc[i][j] = 0.f;

    for (int k0 = 0; k0 < EMB; k0 += BK) {
        // X tile 128x16: 512 float4, 2 per thread
#pragma unroll
        for (int s = 0; s < 2; s++) {
            int e4 = tid + 256 * s;
            int r  = e4 >> 2;
            int c4 = e4 & 3;
            float4 v = *(const float4*)&x[(size_t)(m0 + r) * EMB + k0 + c4 * 4];
            Xs[r][c4 * 4 + 0] = v.x;
            Xs[r][c4 * 4 + 1] = v.y;
            Xs[r][c4 * 4 + 2] = v.z;
            Xs[r][c4 * 4 + 3] = v.w;
        }
        // W tile 16x64: 256 float4, 1 per thread
        {
            int r  = tid >> 4;
            int c4 = tid & 15;
            float4 v = *(const float4*)&W[(size_t)(k0 + r) * HD + c4 * 4];
            *(float4*)&Ws[r][c4 * 4] = v;
        }
        __syncthreads();

#pragma unroll
        for (int kk = 0; kk < BK; kk++) {
            float a[8];
#pragma unroll
            for (int i = 0; i < 8; i++) a[i] = Xs[ty * 8 + i][kk];
            float4 bv = *(const float4*)&Ws[kk][tx * 4];
            float b[4] = {bv.x, bv.y, bv.z, bv.w};
#pragma unroll
            for (int i = 0; i < 8; i++)
#pragma unroll
                for (int j = 0; j < 4; j++)
                    acc[i][j] = fmaf(a[i], b[j], acc[i][j]);
        }
        __syncthreads();
    }

#pragma unroll
    for (int i = 0; i < 8; i++) {
        int r = m0 + ty * 8 + i;
        float4 v = make_float4(acc[i][0], acc[i][1], acc[i][2], acc[i][3]);
        *(float4*)&out[(size_t)r * HD + tx * 4] = v;
    }
}

// ============================================================================
// Flash attention, fp32, BQ=BK=64, online softmax.
// grid=(16 pairs, 8 batches), block=256 (16x16 threads, 4x4 tiles each).
// Block handles q-tiles (p, 31-p): constant 33 kv-tile iterations per block.
// ============================================================================
#define TPAD 68   // transposed-tile row stride (mult of 4 for float4 loads)

__global__ __launch_bounds__(256) void attn_kernel(float* __restrict__ out)
{
    __shared__ float Qt[HD][TPAD];   // [h][qrow]
    __shared__ float Kt[HD][TPAD];   // [h][krow]
    __shared__ float Vs[64][HD];     // [krow][h]
    __shared__ float Pt[64][TPAD];   // [krow][qrow]

    const int b   = blockIdx.y;
    const int p   = blockIdx.x;
    const float* Qg = g_q + (size_t)b * SEQ * HD;
    const float* Kg = g_k + (size_t)b * SEQ * HD;
    const float* Vg = g_v + (size_t)b * SEQ * HD;

    const int tid = threadIdx.x;
    const int ty  = tid >> 4;   // q-row group (4 rows)
    const int tx  = tid & 15;   // col group (4 cols)

    for (int half = 0; half < 2; half++) {
        const int qt = (half == 0) ? p : (31 - p);
        const int q0 = qt * 64;

        __syncthreads();   // prior half's Q reads are long done; cheap safety
        // Load Q tile transposed: Qt[h][qrow]
#pragma unroll
        for (int s = 0; s < 4; s++) {
            int e4 = tid + 256 * s;        // 1024 float4
            int r  = e4 >> 4;              // row 0..63
            int h4 = e4 & 15;
            float4 v = *(const float4*)&Qg[(size_t)(q0 + r) * HD + h4 * 4];
            Qt[h4 * 4 + 0][r] = v.x;
            Qt[h4 * 4 + 1][r] = v.y;
            Qt[h4 * 4 + 2][r] = v.z;
            Qt[h4 * 4 + 3][r] = v.w;
        }

        float o[4][4], m[4], l[4];
#pragma unroll
        for (int i = 0; i < 4; i++) {
            m[i] = -1e30f; l[i] = 0.f;
#pragma unroll
            for (int j = 0; j < 4; j++) o[i][j] = 0.f;
        }

        for (int kt = 0; kt <= qt; kt++) {
            const int k0 = kt * 64;
            __syncthreads();   // prev iter PV done reading Pt/Vs; Kt free
            // Load K transposed + V natural
#pragma unroll
            for (int s = 0; s < 4; s++) {
                int e4 = tid + 256 * s;
                int r  = e4 >> 4;
                int h4 = e4 & 15;
                float4 kv = *(const float4*)&Kg[(size_t)(k0 + r) * HD + h4 * 4];
                Kt[h4 * 4 + 0][r] = kv.x;
                Kt[h4 * 4 + 1][r] = kv.y;
                Kt[h4 * 4 + 2][r] = kv.z;
                Kt[h4 * 4 + 3][r] = kv.w;
                float4 vv = *(const float4*)&Vg[(size_t)(k0 + r) * HD + h4 * 4];
                *(float4*)&Vs[r][h4 * 4] = vv;
            }
            __syncthreads();   // tiles (and Qt on first iter) visible

            // S = Q @ K^T  (reduce over h)
            float s_[4][4];
#pragma unroll
            for (int i = 0; i < 4; i++)
#pragma unroll
                for (int j = 0; j < 4; j++) s_[i][j] = 0.f;
#pragma unroll
            for (int kk = 0; kk < HD; kk++) {
                float4 av = *(const float4*)&Qt[kk][ty * 4];
                float4 bv = *(const float4*)&Kt[kk][tx * 4];
                float a[4] = {av.x, av.y, av.z, av.w};
                float bb[4] = {bv.x, bv.y, bv.z, bv.w};
#pragma unroll
                for (int i = 0; i < 4; i++)
#pragma unroll
                    for (int j = 0; j < 4; j++)
                        s_[i][j] = fmaf(a[i], bb[j], s_[i][j]);
            }

            // scale (NOTE: reference divides by head_size=64, not sqrt) + causal mask
            const float inv_hs = 1.f / 64.f;
            const bool diag = (kt == qt);
#pragma unroll
            for (int i = 0; i < 4; i++)
#pragma unroll
                for (int j = 0; j < 4; j++) {
                    s_[i][j] *= inv_hs;
                    if (diag && (k0 + tx * 4 + j > q0 + ty * 4 + i))
                        s_[i][j] = -1e30f;
                }

            // row max (shuffle across the 16 tx lanes — stays inside half-warp)
            float mt[4];
#pragma unroll
            for (int i = 0; i < 4; i++) {
                mt[i] = fmaxf(fmaxf(s_[i][0], s_[i][1]), fmaxf(s_[i][2], s_[i][3]));
            }
#pragma unroll
            for (int off = 8; off >= 1; off >>= 1)
#pragma unroll
                for (int i = 0; i < 4; i++)
                    mt[i] = fmaxf(mt[i], __shfl_xor_sync(0xffffffffu, mt[i], off));

            float mn[4], c[4], lt[4];
#pragma unroll
            for (int i = 0; i < 4; i++) {
                mn[i] = fmaxf(m[i], mt[i]);
                c[i]  = __expf(m[i] - mn[i]);
            }
            float p_[4][4];
#pragma unroll
            for (int i = 0; i < 4; i++) {
                float acc = 0.f;
#pragma unroll
                for (int j = 0; j < 4; j++) {
                    p_[i][j] = __expf(s_[i][j] - mn[i]);
                    acc += p_[i][j];
                }
                lt[i] = acc;
            }
#pragma unroll
            for (int off = 8; off >= 1; off >>= 1)
#pragma unroll
                for (int i = 0; i < 4; i++)
                    lt[i] += __shfl_xor_sync(0xffffffffu, lt[i], off);
#pragma unroll
            for (int i = 0; i < 4; i++) {
                l[i] = l[i] * c[i] + lt[i];
                m[i] = mn[i];
#pragma unroll
                for (int j = 0; j < 4; j++) o[i][j] *= c[i];
            }

            // write P transposed: Pt[kcol][qrow]
#pragma unroll
            for (int i = 0; i < 4; i++)
#pragma unroll
                for (int j = 0; j < 4; j++)
                    Pt[tx * 4 + j][ty * 4 + i] = p_[i][j];
            __syncthreads();   // Pt ready

            // O += P @ V  (reduce over kv)
#pragma unroll
            for (int kv = 0; kv < 64; kv++) {
                float4 av = *(const float4*)&Pt[kv][ty * 4];
                float4 bv = *(const float4*)&Vs[kv][tx * 4];
                float a[4]  = {av.x, av.y, av.z, av.w};
                float bb[4] = {bv.x, bv.y, bv.z, bv.w};
#pragma unroll
                for (int i = 0; i < 4; i++)
#pragma unroll
                    for (int j = 0; j < 4; j++)
                        o[i][j] = fmaf(a[i], bb[j], o[i][j]);
            }
        }

        // epilogue: out[b][q0+r][h] = o / l
#pragma unroll
        for (int i = 0; i < 4; i++) {
            float invl = 1.f / l[i];
            int r = q0 + ty * 4 + i;
            float4 v = make_float4(o[i][0] * invl, o[i][1] * invl,
                                   o[i][2] * invl, o[i][3] * invl);
            *(float4*)&out[((size_t)b * SEQ + r) * HD + tx * 4] = v;
        }
    }
}

// ============================================================================
extern "C" void kernel_launch(void* const* d_in, const int* in_sizes, int n_in,
                              void* d_out, int out_size)
{
    const float* x  = (const float*)d_in[0];
    const float* Wq = (const float*)d_in[1];
    const float* Wk = (const float*)d_in[2];
    const float* Wv = (const float*)d_in[3];
    float* out = (float*)d_out;

    dim3 gproj(NROWS / 128, 3);
    proj_kernel<<<gproj, 256>>>(x, Wq, Wk, Wv);

    dim3 gattn(16, BATCH);
    attn_kernel<<<gattn, 256>>>(out);
}

// round 2
// speedup vs baseline: 2.0114x; 2.0114x over previous
#include <cuda_runtime.h>
#include <math.h>
#include <stdint.h>

#define BATCH 8
#define SEQ   2048
#define EMB   1024
#define HD    64
#define NROWS (BATCH*SEQ)   // 16384

__device__ float g_q[NROWS*HD];
__device__ float g_k[NROWS*HD];
__device__ float g_v[NROWS*HD];

// ---------------------------------------------------------------------------
__device__ __forceinline__ float cvt_tf32(float x) {
    uint32_t r;
    asm("cvt.rna.tf32.f32 %0, %1;" : "=r"(r) : "f"(x));
    return __uint_as_float(r);
}

__device__ __forceinline__ void mma_m16n8k8(float d[4],
                                            uint32_t a0, uint32_t a1, uint32_t a2, uint32_t a3,
                                            uint32_t b0, uint32_t b1) {
    asm volatile(
        "mma.sync.aligned.m16n8k8.row.col.f32.tf32.tf32.f32 "
        "{%0,%1,%2,%3},{%4,%5,%6,%7},{%8,%9},{%0,%1,%2,%3};\n"
        : "+f"(d[0]), "+f"(d[1]), "+f"(d[2]), "+f"(d[3])
        : "r"(a0), "r"(a1), "r"(a2), "r"(a3), "r"(b0), "r"(b1));
}

// ============================================================================
// Fused projection: q/k/v[M,64] = X[M,1024] @ W{q,k,v}[1024,64], TF32 mma.
// Block 256 thr (8 warps, 2x4). BM=64, BK=32. Warp: 32 rows x 16 cols x 3 outs.
// ============================================================================
#define ASTR 36   // A stride: bank = (4*row + col) % 32 -> conflict-free frags
__global__ __launch_bounds__(256) void proj_kernel(
    const float* __restrict__ x,
    const float* __restrict__ Wq,
    const float* __restrict__ Wk,
    const float* __restrict__ Wv)
{
    __shared__ float As[64 * ASTR];        // [row][k]
    __shared__ float Bs[3][64 * ASTR];     // [out][n][k]  (transposed)

    const float* Ws[3] = {Wq, Wk, Wv};

    const int m0   = blockIdx.x * 64;
    const int tid  = threadIdx.x;
    const int w    = tid >> 5;
    const int lane = tid & 31;
    const int g    = lane >> 2;   // group 0..7
    const int t    = lane & 3;
    const int wm   = w >> 2;      // 0..1 -> 32 rows
    const int wn   = w & 3;       // 0..3 -> 16 cols

    float acc[3][2][2][4];        // [out][m-atom][n-atom][frag]
#pragma unroll
    for (int o = 0; o < 3; o++)
#pragma unroll
        for (int i = 0; i < 2; i++)
#pragma unroll
            for (int j = 0; j < 2; j++)
#pragma unroll
                for (int q = 0; q < 4; q++) acc[o][i][j][q] = 0.f;

    const uint32_t* Au = (const uint32_t*)As;

    for (int k0 = 0; k0 < EMB; k0 += 32) {
        __syncthreads();
        // stage X tile 64x32 (512 f4, 2/thread), tf32-rounded
#pragma unroll
        for (int s = 0; s < 2; s++) {
            int idx = tid + 256 * s;
            int r = idx >> 3, c4 = idx & 7;
            float4 v = *(const float4*)&x[(size_t)(m0 + r) * EMB + k0 + c4 * 4];
            float4 o4 = make_float4(cvt_tf32(v.x), cvt_tf32(v.y), cvt_tf32(v.z), cvt_tf32(v.w));
            *(float4*)&As[r * ASTR + c4 * 4] = o4;
        }
        // stage 3 W tiles 32x64 each, transposed to [n][k]
#pragma unroll
        for (int o = 0; o < 3; o++) {
#pragma unroll
            for (int s = 0; s < 2; s++) {
                int idx = tid + 256 * s;
                int kr = idx >> 4, n4 = idx & 15;
                float4 v = *(const float4*)&Ws[o][(size_t)(k0 + kr) * HD + n4 * 4];
                Bs[o][(n4 * 4 + 0) * ASTR + kr] = cvt_tf32(v.x);
                Bs[o][(n4 * 4 + 1) * ASTR + kr] = cvt_tf32(v.y);
                Bs[o][(n4 * 4 + 2) * ASTR + kr] = cvt_tf32(v.z);
                Bs[o][(n4 * 4 + 3) * ASTR + kr] = cvt_tf32(v.w);
            }
        }
        __syncthreads();

#pragma unroll
        for (int ks = 0; ks < 4; ks++) {
            uint32_t a[2][4];
#pragma unroll
            for (int am = 0; am < 2; am++) {
                int rb = wm * 32 + am * 16;
                a[am][0] = Au[(rb + g) * ASTR + ks * 8 + t];
                a[am][1] = Au[(rb + g + 8) * ASTR + ks * 8 + t];
                a[am][2] = Au[(rb + g) * ASTR + ks * 8 + t + 4];
                a[am][3] = Au[(rb + g + 8) * ASTR + ks * 8 + t + 4];
            }
#pragma unroll
            for (int o = 0; o < 3; o++) {
                const uint32_t* Bu = (const uint32_t*)Bs[o];
#pragma unroll
                for (int bn = 0; bn < 2; bn++) {
                    int nb = wn * 16 + bn * 8;
                    uint32_t b0 = Bu[(nb + g) * ASTR + ks * 8 + t];
                    uint32_t b1 = Bu[(nb + g) * ASTR + ks * 8 + t + 4];
#pragma unroll
                    for (int am = 0; am < 2; am++)
                        mma_m16n8k8(acc[o][am][bn], a[am][0], a[am][1], a[am][2], a[am][3], b0, b1);
                }
            }
        }
    }

    float* outs[3] = {g_q, g_k, g_v};
#pragma unroll
    for (int o = 0; o < 3; o++)
#pragma unroll
        for (int am = 0; am < 2; am++)
#pragma unroll
            for (int bn = 0; bn < 2; bn++) {
                int r0 = m0 + wm * 32 + am * 16 + g;
                int c  = wn * 16 + bn * 8 + 2 * t;
                *(float2*)&outs[o][(size_t)r0 * HD + c] =
                    make_float2(acc[o][am][bn][0], acc[o][am][bn][1]);
                *(float2*)&outs[o][(size_t)(r0 + 8) * HD + c] =
                    make_float2(acc[o][am][bn][2], acc[o][am][bn][3]);
            }
}

// ============================================================================
// Flash attention, TF32 mma. BQ=BK=64, 128 thr / 4 warps, warp = 16 q-rows.
// Q frags in regs; P reuses Q smem buffer (per-warp rows). Heavy tiles first.
// ============================================================================
#define QSTR 68   // A/K pattern: bank = 4*row + col
#define VSTR 72   // V  pattern: bank = 8*row + col
#define SM_QP 0
#define SM_K  (64*QSTR)
#define SM_V  (2*64*QSTR)
#define SM_TOT (2*64*QSTR + 64*VSTR)   // floats

__global__ __launch_bounds__(128) void attn_kernel(float* __restrict__ out)
{
    extern __shared__ float sm[];
    float* QP = sm + SM_QP;
    float* Ks = sm + SM_K;
    float* Vs = sm + SM_V;
    const uint32_t* QPu = (const uint32_t*)QP;
    const uint32_t* Ku  = (const uint32_t*)Ks;
    const uint32_t* Vu  = (const uint32_t*)Vs;

    const int bx = blockIdx.x;
    const int b  = bx & 7;
    const int qt = 31 - (bx >> 3);      // heavy-first
    const int q0 = qt * 64;

    const float* Qg = g_q + (size_t)b * SEQ * HD;
    const float* Kg = g_k + (size_t)b * SEQ * HD;
    const float* Vg = g_v + (size_t)b * SEQ * HD;

    const int tid  = threadIdx.x;
    const int w    = tid >> 5;
    const int lane = tid & 31;
    const int g    = lane >> 2;
    const int t    = lane & 3;
    const int qb   = w * 16;           // warp q-row base within tile

    // stage Q (tf32) into QP
#pragma unroll
    for (int s = 0; s < 8; s++) {
        int idx = tid + 128 * s;
        int r = idx >> 4, c4 = idx & 15;
        float4 v = *(const float4*)&Qg[(size_t)(q0 + r) * HD + c4 * 4];
        float4 o4 = make_float4(cvt_tf32(v.x), cvt_tf32(v.y), cvt_tf32(v.z), cvt_tf32(v.w));
        *(float4*)&QP[r * QSTR + c4 * 4] = o4;
    }
    __syncthreads();

    // Q fragments in registers (held for entire kv loop)
    uint32_t aQ[8][4];
#pragma unroll
    for (int ks = 0; ks < 8; ks++) {
        aQ[ks][0] = QPu[(qb + g) * QSTR + ks * 8 + t];
        aQ[ks][1] = QPu[(qb + g + 8) * QSTR + ks * 8 + t];
        aQ[ks][2] = QPu[(qb + g) * QSTR + ks * 8 + t + 4];
        aQ[ks][3] = QPu[(qb + g + 8) * QSTR + ks * 8 + t + 4];
    }

    float o_[8][4];
    float m0v = -1e30f, m1v = -1e30f, l0 = 0.f, l1 = 0.f;
#pragma unroll
    for (int bn = 0; bn < 8; bn++)
#pragma unroll
        for (int q = 0; q < 4; q++) o_[bn][q] = 0.f;

    const float inv_hs = 1.f / 64.f;

    for (int kt = 0; kt <= qt; kt++) {
        const int k0 = kt * 64;
        __syncthreads();
        // stage K, V (tf32)
#pragma unroll
        for (int s = 0; s < 8; s++) {
            int idx = tid + 128 * s;
            int r = idx >> 4, c4 = idx & 15;
            float4 kv = *(const float4*)&Kg[(size_t)(k0 + r) * HD + c4 * 4];
            *(float4*)&Ks[r * QSTR + c4 * 4] =
                make_float4(cvt_tf32(kv.x), cvt_tf32(kv.y), cvt_tf32(kv.z), cvt_tf32(kv.w));
            float4 vv = *(const float4*)&Vg[(size_t)(k0 + r) * HD + c4 * 4];
            *(float4*)&Vs[r * VSTR + c4 * 4] =
                make_float4(cvt_tf32(vv.x), cvt_tf32(vv.y), cvt_tf32(vv.z), cvt_tf32(vv.w));
        }
        __syncthreads();

        // S = Q @ K^T
        float sa[8][4];
#pragma unroll
        for (int bn = 0; bn < 8; bn++)
#pragma unroll
            for (int q = 0; q < 4; q++) sa[bn][q] = 0.f;
#pragma unroll
        for (int ks = 0; ks < 8; ks++) {
#pragma unroll
            for (int bn = 0; bn < 8; bn++) {
                uint32_t b0 = Ku[(bn * 8 + g) * QSTR + ks * 8 + t];
                uint32_t b1 = Ku[(bn * 8 + g) * QSTR + ks * 8 + t + 4];
                mma_m16n8k8(sa[bn], aQ[ks][0], aQ[ks][1], aQ[ks][2], aQ[ks][3], b0, b1);
            }
        }

        // scale + causal mask (reference divides by head_size, not sqrt)
        const bool diag = (kt == qt);
#pragma unroll
        for (int bn = 0; bn < 8; bn++)
#pragma unroll
            for (int q = 0; q < 4; q++) {
                float v = sa[bn][q] * inv_hs;
                if (diag) {
                    int col = k0 + bn * 8 + 2 * t + (q & 1);
                    int row = q0 + qb + g + ((q >= 2) ? 8 : 0);
                    if (col > row) v = -1e30f;
                }
                sa[bn][q] = v;
            }

        // row max (row0 = g, row1 = g+8)
        float mt0 = -1e30f, mt1 = -1e30f;
#pragma unroll
        for (int bn = 0; bn < 8; bn++) {
            mt0 = fmaxf(mt0, fmaxf(sa[bn][0], sa[bn][1]));
            mt1 = fmaxf(mt1, fmaxf(sa[bn][2], sa[bn][3]));
        }
#pragma unroll
        for (int off = 1; off <= 2; off <<= 1) {
            mt0 = fmaxf(mt0, __shfl_xor_sync(0xffffffffu, mt0, off));
            mt1 = fmaxf(mt1, __shfl_xor_sync(0xffffffffu, mt1, off));
        }
        float mn0 = fmaxf(m0v, mt0), mn1 = fmaxf(m1v, mt1);
        float c0 = __expf(m0v - mn0), c1 = __expf(m1v - mn1);

        // P = exp(S - m), row sums, write P (tf32) into QP (own rows only)
        float lt0 = 0.f, lt1 = 0.f;
#pragma unroll
        for (int bn = 0; bn < 8; bn++) {
            float p0 = __expf(sa[bn][0] - mn0);
            float p1 = __expf(sa[bn][1] - mn0);
            float p2 = __expf(sa[bn][2] - mn1);
            float p3 = __expf(sa[bn][3] - mn1);
            lt0 += p0 + p1;  lt1 += p2 + p3;
            *(float2*)&QP[(qb + g) * QSTR + bn * 8 + 2 * t] =
                make_float2(cvt_tf32(p0), cvt_tf32(p1));
            *(float2*)&QP[(qb + g + 8) * QSTR + bn * 8 + 2 * t] =
                make_float2(cvt_tf32(p2), cvt_tf32(p3));
            o_[bn][0] *= c0; o_[bn][1] *= c0; o_[bn][2] *= c1; o_[bn][3] *= c1;
        }
#pragma unroll
        for (int off = 1; off <= 2; off <<= 1) {
            lt0 += __shfl_xor_sync(0xffffffffu, lt0, off);
            lt1 += __shfl_xor_sync(0xffffffffu, lt1, off);
        }
        l0 = l0 * c0 + lt0;  l1 = l1 * c1 + lt1;
        m0v = mn0;  m1v = mn1;
        __syncwarp();

        // O += P @ V
#pragma unroll
        for (int ks = 0; ks < 8; ks++) {
            uint32_t a0 = QPu[(qb + g) * QSTR + ks * 8 + t];
            uint32_t a1 = QPu[(qb + g + 8) * QSTR + ks * 8 + t];
            uint32_t a2 = QPu[(qb + g) * QSTR + ks * 8 + t + 4];
            uint32_t a3 = QPu[(qb + g + 8) * QSTR + ks * 8 + t + 4];
#pragma unroll
            for (int bn = 0; bn < 8; bn++) {
                uint32_t b0 = Vu[(ks * 8 + t) * VSTR + bn * 8 + g];
                uint32_t b1 = Vu[(ks * 8 + t + 4) * VSTR + bn * 8 + g];
                mma_m16n8k8(o_[bn], a0, a1, a2, a3, b0, b1);
            }
        }
        __syncwarp();   // P reads done before next iter overwrites (own rows)
    }

    // epilogue
    float i0 = 1.f / l0, i1 = 1.f / l1;
    int r0 = q0 + qb + g;
#pragma unroll
    for (int bn = 0; bn < 8; bn++) {
        int c = bn * 8 + 2 * t;
        *(float2*)&out[((size_t)b * SEQ + r0) * HD + c] =
            make_float2(o_[bn][0] * i0, o_[bn][1] * i0);
        *(float2*)&out[((size_t)b * SEQ + r0 + 8) * HD + c] =
            make_float2(o_[bn][2] * i1, o_[bn][3] * i1);
    }
}

// ============================================================================
extern "C" void kernel_launch(void* const* d_in, const int* in_sizes, int n_in,
                              void* d_out, int out_size)
{
    const float* x  = (const float*)d_in[0];
    const float* Wq = (const float*)d_in[1];
    const float* Wk = (const float*)d_in[2];
    const float* Wv = (const float*)d_in[3];
    float* out = (float*)d_out;

    proj_kernel<<<NROWS / 64, 256>>>(x, Wq, Wk, Wv);

    cudaFuncSetAttribute(attn_kernel, cudaFuncAttributeMaxDynamicSharedMemorySize,
                         SM_TOT * sizeof(float));
    attn_kernel<<<256, 128, SM_TOT * sizeof(float)>>>(out);
}

// round 3
// speedup vs baseline: 3.1124x; 1.5474x over previous
#include <cuda_runtime.h>
#include <math.h>
#include <stdint.h>

#define BATCH 8
#define SEQ   2048
#define EMB   1024
#define HD    64
#define NROWS (BATCH*SEQ)   // 16384

__device__ float g_q[NROWS*HD];
__device__ float g_k[NROWS*HD];
__device__ float g_v[NROWS*HD];
// flash-decoding partials (2 kv-halves): unnormalized O, running max m, sum l
__device__ float g_po[2][NROWS*HD];
__device__ float g_pm[2][NROWS];
__device__ float g_pl[2][NROWS];

// ---------------------------------------------------------------------------
__device__ __forceinline__ float cvt_tf32(float x) {
    uint32_t r;
    asm("cvt.rna.tf32.f32 %0, %1;" : "=r"(r) : "f"(x));
    return __uint_as_float(r);
}

__device__ __forceinline__ void mma_m16n8k8(float d[4],
                                            uint32_t a0, uint32_t a1, uint32_t a2, uint32_t a3,
                                            uint32_t b0, uint32_t b1) {
    asm volatile(
        "mma.sync.aligned.m16n8k8.row.col.f32.tf32.tf32.f32 "
        "{%0,%1,%2,%3},{%4,%5,%6,%7},{%8,%9},{%0,%1,%2,%3};\n"
        : "+f"(d[0]), "+f"(d[1]), "+f"(d[2]), "+f"(d[3])
        : "r"(a0), "r"(a1), "r"(a2), "r"(a3), "r"(b0), "r"(b1));
}

// ============================================================================
// Fused projection: q/k/v[M,64] = X[M,1024] @ W{q,k,v}[1024,64], TF32 mma.
// Block 256 thr (8 warps, 2x4). BM=64, BK=32. Warp: 32 rows x 16 cols x 3 outs.
// W staged in natural [k][n] layout, stride 72 -> conflict-free f4 STS + frags.
// ============================================================================
#define ASTR 36
#define BSTR 72
__global__ __launch_bounds__(256) void proj_kernel(
    const float* __restrict__ x,
    const float* __restrict__ Wq,
    const float* __restrict__ Wk,
    const float* __restrict__ Wv)
{
    __shared__ float As[64 * ASTR];        // [m][k]
    __shared__ float Bs[3][32 * BSTR];     // [out][k][n]

    const float* Ws[3] = {Wq, Wk, Wv};

    const int m0   = blockIdx.x * 64;
    const int tid  = threadIdx.x;
    const int w    = tid >> 5;
    const int lane = tid & 31;
    const int g    = lane >> 2;
    const int t    = lane & 3;
    const int wm   = w >> 2;      // 0..1 -> 32 rows
    const int wn   = w & 3;       // 0..3 -> 16 cols

    float acc[3][2][2][4];
#pragma unroll
    for (int o = 0; o < 3; o++)
#pragma unroll
        for (int i = 0; i < 2; i++)
#pragma unroll
            for (int j = 0; j < 2; j++)
#pragma unroll
                for (int q = 0; q < 4; q++) acc[o][i][j][q] = 0.f;

    const uint32_t* Au = (const uint32_t*)As;

    for (int k0 = 0; k0 < EMB; k0 += 32) {
        __syncthreads();
        // stage X tile 64x32 (tf32-rounded)
#pragma unroll
        for (int s = 0; s < 2; s++) {
            int idx = tid + 256 * s;
            int r = idx >> 3, c4 = idx & 7;
            float4 v = *(const float4*)&x[(size_t)(m0 + r) * EMB + k0 + c4 * 4];
            *(float4*)&As[r * ASTR + c4 * 4] =
                make_float4(cvt_tf32(v.x), cvt_tf32(v.y), cvt_tf32(v.z), cvt_tf32(v.w));
        }
        // stage 3 W tiles 32x64, natural [k][n] layout
#pragma unroll
        for (int o = 0; o < 3; o++) {
#pragma unroll
            for (int s = 0; s < 2; s++) {
                int idx = tid + 256 * s;
                int kr = idx >> 4, c4 = idx & 15;
                float4 v = *(const float4*)&Ws[o][(size_t)(k0 + kr) * HD + c4 * 4];
                *(float4*)&Bs[o][kr * BSTR + c4 * 4] =
                    make_float4(cvt_tf32(v.x), cvt_tf32(v.y), cvt_tf32(v.z), cvt_tf32(v.w));
            }
        }
        __syncthreads();

#pragma unroll
        for (int ks = 0; ks < 4; ks++) {
            uint32_t a[2][4];
#pragma unroll
            for (int am = 0; am < 2; am++) {
                int rb = wm * 32 + am * 16;
                a[am][0] = Au[(rb + g) * ASTR + ks * 8 + t];
                a[am][1] = Au[(rb + g + 8) * ASTR + ks * 8 + t];
                a[am][2] = Au[(rb + g) * ASTR + ks * 8 + t + 4];
                a[am][3] = Au[(rb + g + 8) * ASTR + ks * 8 + t + 4];
            }
#pragma unroll
            for (int o = 0; o < 3; o++) {
                const uint32_t* Bu = (const uint32_t*)Bs[o];
#pragma unroll
                for (int bn = 0; bn < 2; bn++) {
                    int nb = wn * 16 + bn * 8;
                    uint32_t b0 = Bu[(ks * 8 + t) * BSTR + nb + g];
                    uint32_t b1 = Bu[(ks * 8 + t + 4) * BSTR + nb + g];
#pragma unroll
                    for (int am = 0; am < 2; am++)
                        mma_m16n8k8(acc[o][am][bn], a[am][0], a[am][1], a[am][2], a[am][3], b0, b1);
                }
            }
        }
    }

    float* outs[3] = {g_q, g_k, g_v};
#pragma unroll
    for (int o = 0; o < 3; o++)
#pragma unroll
        for (int am = 0; am < 2; am++)
#pragma unroll
            for (int bn = 0; bn < 2; bn++) {
                int r0 = m0 + wm * 32 + am * 16 + g;
                int c  = wn * 16 + bn * 8 + 2 * t;
                *(float2*)&outs[o][(size_t)r0 * HD + c] =
                    make_float2(acc[o][am][bn][0], acc[o][am][bn][1]);
                *(float2*)&outs[o][(size_t)(r0 + 8) * HD + c] =
                    make_float2(acc[o][am][bn][2], acc[o][am][bn][3]);
            }
}

// ============================================================================
// Flash attention, TF32 mma, kv-split x2 (flash-decoding style).
// grid = 512: qt (heavy-first) x batch x half. 128 thr / 4 warps.
// Writes unnormalized partials; merge_kernel combines.
// ============================================================================
#define QSTR 68
#define VSTR 72
#define SM_QP 0
#define SM_K  (64*QSTR)
#define SM_V  (2*64*QSTR)
#define SM_TOT (2*64*QSTR + 64*VSTR)   // floats (~53KB)

__global__ __launch_bounds__(128, 4) void attn_kernel()
{
    extern __shared__ float sm[];
    float* QP = sm + SM_QP;
    float* Ks = sm + SM_K;
    float* Vs = sm + SM_V;
    const uint32_t* QPu = (const uint32_t*)QP;
    const uint32_t* Ku  = (const uint32_t*)Ks;
    const uint32_t* Vu  = (const uint32_t*)Vs;

    const int bx   = blockIdx.x;
    const int qt   = 31 - (bx >> 4);      // heavy-first
    const int sub  = bx & 15;
    const int b    = sub >> 1;
    const int half = sub & 1;
    const int q0   = qt * 64;

    const int nk     = qt + 1;
    const int nhalf  = (nk + 1) >> 1;
    const int kt_beg = half ? nhalf : 0;
    const int kt_end = half ? nk : nhalf;

    const float* Qg = g_q + (size_t)b * SEQ * HD;
    const float* Kg = g_k + (size_t)b * SEQ * HD;
    const float* Vg = g_v + (size_t)b * SEQ * HD;

    const int tid  = threadIdx.x;
    const int w    = tid >> 5;
    const int lane = tid & 31;
    const int g    = lane >> 2;
    const int t    = lane & 3;
    const int qb   = w * 16;

    // stage Q (tf32)
#pragma unroll
    for (int s = 0; s < 8; s++) {
        int idx = tid + 128 * s;
        int r = idx >> 4, c4 = idx & 15;
        float4 v = *(const float4*)&Qg[(size_t)(q0 + r) * HD + c4 * 4];
        *(float4*)&QP[r * QSTR + c4 * 4] =
            make_float4(cvt_tf32(v.x), cvt_tf32(v.y), cvt_tf32(v.z), cvt_tf32(v.w));
    }
    __syncthreads();

    uint32_t aQ[8][4];
#pragma unroll
    for (int ks = 0; ks < 8; ks++) {
        aQ[ks][0] = QPu[(qb + g) * QSTR + ks * 8 + t];
        aQ[ks][1] = QPu[(qb + g + 8) * QSTR + ks * 8 + t];
        aQ[ks][2] = QPu[(qb + g) * QSTR + ks * 8 + t + 4];
        aQ[ks][3] = QPu[(qb + g + 8) * QSTR + ks * 8 + t + 4];
    }

    float o_[8][4];
    float m0v = -1e30f, m1v = -1e30f, l0 = 0.f, l1 = 0.f;
#pragma unroll
    for (int bn = 0; bn < 8; bn++)
#pragma unroll
        for (int q = 0; q < 4; q++) o_[bn][q] = 0.f;

    const float inv_hs = 1.f / 64.f;

    for (int kt = kt_beg; kt < kt_end; kt++) {
        const int k0 = kt * 64;
        __syncthreads();
#pragma unroll
        for (int s = 0; s < 8; s++) {
            int idx = tid + 128 * s;
            int r = idx >> 4, c4 = idx & 15;
            float4 kv = *(const float4*)&Kg[(size_t)(k0 + r) * HD + c4 * 4];
            *(float4*)&Ks[r * QSTR + c4 * 4] =
                make_float4(cvt_tf32(kv.x), cvt_tf32(kv.y), cvt_tf32(kv.z), cvt_tf32(kv.w));
            float4 vv = *(const float4*)&Vg[(size_t)(k0 + r) * HD + c4 * 4];
            *(float4*)&Vs[r * VSTR + c4 * 4] =
                make_float4(cvt_tf32(vv.x), cvt_tf32(vv.y), cvt_tf32(vv.z), cvt_tf32(vv.w));
        }
        __syncthreads();

        // S = Q @ K^T
        float sa[8][4];
#pragma unroll
        for (int bn = 0; bn < 8; bn++)
#pragma unroll
            for (int q = 0; q < 4; q++) sa[bn][q] = 0.f;
#pragma unroll
        for (int ks = 0; ks < 8; ks++) {
#pragma unroll
            for (int bn = 0; bn < 8; bn++) {
                uint32_t b0 = Ku[(bn * 8 + g) * QSTR + ks * 8 + t];
                uint32_t b1 = Ku[(bn * 8 + g) * QSTR + ks * 8 + t + 4];
                mma_m16n8k8(sa[bn], aQ[ks][0], aQ[ks][1], aQ[ks][2], aQ[ks][3], b0, b1);
            }
        }

        const bool diag = (kt == qt);
#pragma unroll
        for (int bn = 0; bn < 8; bn++)
#pragma unroll
            for (int q = 0; q < 4; q++) {
                float v = sa[bn][q] * inv_hs;
                if (diag) {
                    int col = k0 + bn * 8 + 2 * t + (q & 1);
                    int row = q0 + qb + g + ((q >= 2) ? 8 : 0);
                    if (col > row) v = -1e30f;
                }
                sa[bn][q] = v;
            }

        float mt0 = -1e30f, mt1 = -1e30f;
#pragma unroll
        for (int bn = 0; bn < 8; bn++) {
            mt0 = fmaxf(mt0, fmaxf(sa[bn][0], sa[bn][1]));
            mt1 = fmaxf(mt1, fmaxf(sa[bn][2], sa[bn][3]));
        }
#pragma unroll
        for (int off = 1; off <= 2; off <<= 1) {
            mt0 = fmaxf(mt0, __shfl_xor_sync(0xffffffffu, mt0, off));
            mt1 = fmaxf(mt1, __shfl_xor_sync(0xffffffffu, mt1, off));
        }
        float mn0 = fmaxf(m0v, mt0), mn1 = fmaxf(m1v, mt1);
        float c0 = __expf(m0v - mn0), c1 = __expf(m1v - mn1);

        float lt0 = 0.f, lt1 = 0.f;
#pragma unroll
        for (int bn = 0; bn < 8; bn++) {
            float p0 = __expf(sa[bn][0] - mn0);
            float p1 = __expf(sa[bn][1] - mn0);
            float p2 = __expf(sa[bn][2] - mn1);
            float p3 = __expf(sa[bn][3] - mn1);
            lt0 += p0 + p1;  lt1 += p2 + p3;
            *(float2*)&QP[(qb + g) * QSTR + bn * 8 + 2 * t] =
                make_float2(cvt_tf32(p0), cvt_tf32(p1));
            *(float2*)&QP[(qb + g + 8) * QSTR + bn * 8 + 2 * t] =
                make_float2(cvt_tf32(p2), cvt_tf32(p3));
            o_[bn][0] *= c0; o_[bn][1] *= c0; o_[bn][2] *= c1; o_[bn][3] *= c1;
        }
#pragma unroll
        for (int off = 1; off <= 2; off <<= 1) {
            lt0 += __shfl_xor_sync(0xffffffffu, lt0, off);
            lt1 += __shfl_xor_sync(0xffffffffu, lt1, off);
        }
        l0 = l0 * c0 + lt0;  l1 = l1 * c1 + lt1;
        m0v = mn0;  m1v = mn1;
        __syncwarp();

        // O += P @ V
#pragma unroll
        for (int ks = 0; ks < 8; ks++) {
            uint32_t a0 = QPu[(qb + g) * QSTR + ks * 8 + t];
            uint32_t a1 = QPu[(qb + g + 8) * QSTR + ks * 8 + t];
            uint32_t a2 = QPu[(qb + g) * QSTR + ks * 8 + t + 4];
            uint32_t a3 = QPu[(qb + g + 8) * QSTR + ks * 8 + t + 4];
#pragma unroll
            for (int bn = 0; bn < 8; bn++) {
                uint32_t b0 = Vu[(ks * 8 + t) * VSTR + bn * 8 + g];
                uint32_t b1 = Vu[(ks * 8 + t + 4) * VSTR + bn * 8 + g];
                mma_m16n8k8(o_[bn], a0, a1, a2, a3, b0, b1);
            }
        }
        __syncwarp();
    }

    // write unnormalized partials
    const int r0g = b * SEQ + q0 + qb + g;
    if (t == 0) {
        g_pm[half][r0g]     = m0v;  g_pl[half][r0g]     = l0;
        g_pm[half][r0g + 8] = m1v;  g_pl[half][r0g + 8] = l1;
    }
#pragma unroll
    for (int bn = 0; bn < 8; bn++) {
        int c = bn * 8 + 2 * t;
        *(float2*)&g_po[half][(size_t)r0g * HD + c] =
            make_float2(o_[bn][0], o_[bn][1]);
        *(float2*)&g_po[half][(size_t)(r0g + 8) * HD + c] =
            make_float2(o_[bn][2], o_[bn][3]);
    }
}

// ============================================================================
// Merge the two kv-half partials: out = (o0*e^{m0-M} + o1*e^{m1-M}) / L
// ============================================================================
__global__ __launch_bounds__(256) void merge_kernel(float* __restrict__ out)
{
    int gid = blockIdx.x * 256 + threadIdx.x;   // NROWS*16 total
    int row = gid >> 4;
    int c   = (gid & 15) * 4;
    float m0 = g_pm[0][row], m1 = g_pm[1][row];
    float l0 = g_pl[0][row], l1 = g_pl[1][row];
    float M  = fmaxf(m0, m1);
    float w0 = __expf(m0 - M), w1 = __expf(m1 - M);
    float inv = 1.f / (l0 * w0 + l1 * w1);
    float4 a = *(const float4*)&g_po[0][(size_t)row * HD + c];
    float4 b = *(const float4*)&g_po[1][(size_t)row * HD + c];
    float4 r;
    r.x = (a.x * w0 + b.x * w1) * inv;
    r.y = (a.y * w0 + b.y * w1) * inv;
    r.z = (a.z * w0 + b.z * w1) * inv;
    r.w = (a.w * w0 + b.w * w1) * inv;
    *(float4*)&out[(size_t)row * HD + c] = r;
}

// ============================================================================
extern "C" void kernel_launch(void* const* d_in, const int* in_sizes, int n_in,
                              void* d_out, int out_size)
{
    const float* x  = (const float*)d_in[0];
    const float* Wq = (const float*)d_in[1];
    const float* Wk = (const float*)d_in[2];
    const float* Wv = (const float*)d_in[3];
    float* out = (float*)d_out;

    proj_kernel<<<NROWS / 64, 256>>>(x, Wq, Wk, Wv);

    cudaFuncSetAttribute(attn_kernel, cudaFuncAttributeMaxDynamicSharedMemorySize,
                         SM_TOT * sizeof(float));
    attn_kernel<<<512, 128, SM_TOT * sizeof(float)>>>();

    merge_kernel<<<NROWS * 16 / 256, 256>>>(out);
}

// round 4
// speedup vs baseline: 3.2327x; 1.0387x over previous
#include <cuda_runtime.h>
#include <math.h>
#include <stdint.h>

#define BATCH 8
#define SEQ   2048
#define EMB   1024
#define HD    64
#define NROWS (BATCH*SEQ)   // 16384

__device__ float g_q[NROWS*HD];
__device__ float g_k[NROWS*HD];
__device__ float g_v[NROWS*HD];
__device__ float g_wt[3][EMB*HD];   // tf32-pre-rounded weights
// flash-decoding partials
__device__ float g_po[2][NROWS*HD];
__device__ float g_pm[2][NROWS];
__device__ float g_pl[2][NROWS];

// ---------------------------------------------------------------------------
__device__ __forceinline__ float cvt_tf32(float x) {
    uint32_t r;
    asm("cvt.rna.tf32.f32 %0, %1;" : "=r"(r) : "f"(x));
    return __uint_as_float(r);
}
__device__ __forceinline__ uint32_t cvt_tf32_u(float x) {
    uint32_t r;
    asm("cvt.rna.tf32.f32 %0, %1;" : "=r"(r) : "f"(x));
    return r;
}
__device__ __forceinline__ void mma_m16n8k8(float d[4],
                                            uint32_t a0, uint32_t a1, uint32_t a2, uint32_t a3,
                                            uint32_t b0, uint32_t b1) {
    asm volatile(
        "mma.sync.aligned.m16n8k8.row.col.f32.tf32.tf32.f32 "
        "{%0,%1,%2,%3},{%4,%5,%6,%7},{%8,%9},{%0,%1,%2,%3};\n"
        : "+f"(d[0]), "+f"(d[1]), "+f"(d[2]), "+f"(d[3])
        : "r"(a0), "r"(a1), "r"(a2), "r"(a3), "r"(b0), "r"(b1));
}
__device__ __forceinline__ void cp16(uint32_t smem_dst, const void* gsrc) {
    asm volatile("cp.async.cg.shared.global [%0], [%1], 16;\n"
                 :: "r"(smem_dst), "l"(gsrc));
}

// ============================================================================
// W -> tf32 pre-round (768KB, ~2us)
// ============================================================================
__global__ __launch_bounds__(256) void wcvt_kernel(
    const float* __restrict__ Wq, const float* __restrict__ Wk,
    const float* __restrict__ Wv)
{
    const float* src[3] = {Wq, Wk, Wv};
    int gid = blockIdx.x * 256 + threadIdx.x;     // 3 * 16384 f4
    int o   = gid / (EMB * HD / 4);
    int e4  = gid % (EMB * HD / 4);
    float4 v = *(const float4*)&src[o][e4 * 4];
    *(float4*)&g_wt[o][e4 * 4] =
        make_float4(cvt_tf32(v.x), cvt_tf32(v.y), cvt_tf32(v.z), cvt_tf32(v.w));
}

// ============================================================================
// Projection: out_o[M,64] = X[M,1024] @ W_o[1024,64].  One output per block.
// grid = 768 (m-tile major, o minor -> x L2 reuse). 256 thr / 8 warps (2x4).
// BM=64, BN=64, BK=32, cp.async 2-stage double buffer.
// ============================================================================
#define ASTR 36   // bank = 4m+k  -> conflict-free A frags
#define BSTR 72   // bank = 8k+n  -> conflict-free B frags
__global__ __launch_bounds__(256) void proj_kernel(const float* __restrict__ x)
{
    __shared__ float As[2][64 * ASTR];   // raw fp32 x tile [m][k]
    __shared__ float Bs[2][32 * BSTR];   // tf32 W tile [k][n]

    const int bx = blockIdx.x;
    const int o  = bx % 3;
    const int m0 = (bx / 3) * 64;
    const float* W = g_wt[o];
    float* out = (o == 0) ? g_q : (o == 1) ? g_k : g_v;

    const int tid  = threadIdx.x;
    const int w    = tid >> 5;
    const int lane = tid & 31;
    const int g    = lane >> 2;
    const int t    = lane & 3;
    const int wm   = w >> 2;      // 0..1
    const int wn   = w & 3;       // 0..3

    uint32_t As_b = __cvta_generic_to_shared(&As[0][0]);
    uint32_t Bs_b = __cvta_generic_to_shared(&Bs[0][0]);

    auto stage = [&](int buf, int k0) {
#pragma unroll
        for (int s = 0; s < 2; s++) {               // As: 512 f4
            int idx = tid + 256 * s;
            int r = idx >> 3, c4 = idx & 7;
            cp16(As_b + (buf * 64 * ASTR + r * ASTR + c4 * 4) * 4,
                 &x[(size_t)(m0 + r) * EMB + k0 + c4 * 4]);
        }
#pragma unroll
        for (int s = 0; s < 2; s++) {               // Bs: 512 f4
            int idx = tid + 256 * s;
            int kr = idx >> 4, c4 = idx & 15;
            cp16(Bs_b + (buf * 32 * BSTR + kr * BSTR + c4 * 4) * 4,
                 &W[(size_t)(k0 + kr) * HD + c4 * 4]);
        }
        asm volatile("cp.async.commit_group;\n");
    };

    float acc[2][2][4];
#pragma unroll
    for (int i = 0; i < 2; i++)
#pragma unroll
        for (int j = 0; j < 2; j++)
#pragma unroll
            for (int q = 0; q < 4; q++) acc[i][j][q] = 0.f;

    stage(0, 0);

    for (int k0 = 0; k0 < EMB; k0 += 32) {
        const int buf = (k0 >> 5) & 1;
        if (k0 + 32 < EMB) {
            stage(buf ^ 1, k0 + 32);
            asm volatile("cp.async.wait_group 1;\n");
        } else {
            asm volatile("cp.async.wait_group 0;\n");
        }
        __syncthreads();

        const float*    Af = As[buf];
        const uint32_t* Bu = (const uint32_t*)Bs[buf];
#pragma unroll
        for (int ks = 0; ks < 4; ks++) {
            uint32_t a[2][4];
#pragma unroll
            for (int am = 0; am < 2; am++) {
                int rb = wm * 32 + am * 16;
                a[am][0] = cvt_tf32_u(Af[(rb + g) * ASTR + ks * 8 + t]);
                a[am][1] = cvt_tf32_u(Af[(rb + g + 8) * ASTR + ks * 8 + t]);
                a[am][2] = cvt_tf32_u(Af[(rb + g) * ASTR + ks * 8 + t + 4]);
                a[am][3] = cvt_tf32_u(Af[(rb + g + 8) * ASTR + ks * 8 + t + 4]);
            }
#pragma unroll
            for (int bn = 0; bn < 2; bn++) {
                int nb = wn * 16 + bn * 8;
                uint32_t b0 = Bu[(ks * 8 + t) * BSTR + nb + g];
                uint32_t b1 = Bu[(ks * 8 + t + 4) * BSTR + nb + g];
#pragma unroll
                for (int am = 0; am < 2; am++)
                    mma_m16n8k8(acc[am][bn], a[am][0], a[am][1], a[am][2], a[am][3], b0, b1);
            }
        }
        __syncthreads();   // compute done before next stage overwrites this buf
    }

#pragma unroll
    for (int am = 0; am < 2; am++)
#pragma unroll
        for (int bn = 0; bn < 2; bn++) {
            int r0 = m0 + wm * 32 + am * 16 + g;
            int c  = wn * 16 + bn * 8 + 2 * t;
            *(float2*)&out[(size_t)r0 * HD + c] = make_float2(acc[am][bn][0], acc[am][bn][1]);
            *(float2*)&out[(size_t)(r0 + 8) * HD + c] = make_float2(acc[am][bn][2], acc[am][bn][3]);
        }
}

// ============================================================================
// Flash attention (unchanged from R3): TF32 mma, kv-split x2, grid 512.
// ============================================================================
#define QSTR 68
#define VSTR 72
#define SM_QP 0
#define SM_K  (64*QSTR)
#define SM_V  (2*64*QSTR)
#define SM_TOT (2*64*QSTR + 64*VSTR)

__global__ __launch_bounds__(128, 4) void attn_kernel()
{
    extern __shared__ float sm[];
    float* QP = sm + SM_QP;
    float* Ks = sm + SM_K;
    float* Vs = sm + SM_V;
    const uint32_t* QPu = (const uint32_t*)QP;
    const uint32_t* Ku  = (const uint32_t*)Ks;
    const uint32_t* Vu  = (const uint32_t*)Vs;

    const int bx   = blockIdx.x;
    const int qt   = 31 - (bx >> 4);
    const int sub  = bx & 15;
    const int b    = sub >> 1;
    const int half = sub & 1;
    const int q0   = qt * 64;

    const int nk     = qt + 1;
    const int nhalf  = (nk + 1) >> 1;
    const int kt_beg = half ? nhalf : 0;
    const int kt_end = half ? nk : nhalf;

    const float* Qg = g_q + (size_t)b * SEQ * HD;
    const float* Kg = g_k + (size_t)b * SEQ * HD;
    const float* Vg = g_v + (size_t)b * SEQ * HD;

    const int tid  = threadIdx.x;
    const int w    = tid >> 5;
    const int lane = tid & 31;
    const int g    = lane >> 2;
    const int t    = lane & 3;
    const int qb   = w * 16;

#pragma unroll
    for (int s = 0; s < 8; s++) {
        int idx = tid + 128 * s;
        int r = idx >> 4, c4 = idx & 15;
        float4 v = *(const float4*)&Qg[(size_t)(q0 + r) * HD + c4 * 4];
        *(float4*)&QP[r * QSTR + c4 * 4] =
            make_float4(cvt_tf32(v.x), cvt_tf32(v.y), cvt_tf32(v.z), cvt_tf32(v.w));
    }
    __syncthreads();

    uint32_t aQ[8][4];
#pragma unroll
    for (int ks = 0; ks < 8; ks++) {
        aQ[ks][0] = QPu[(qb + g) * QSTR + ks * 8 + t];
        aQ[ks][1] = QPu[(qb + g + 8) * QSTR + ks * 8 + t];
        aQ[ks][2] = QPu[(qb + g) * QSTR + ks * 8 + t + 4];
        aQ[ks][3] = QPu[(qb + g + 8) * QSTR + ks * 8 + t + 4];
    }

    float o_[8][4];
    float m0v = -1e30f, m1v = -1e30f, l0 = 0.f, l1 = 0.f;
#pragma unroll
    for (int bn = 0; bn < 8; bn++)
#pragma unroll
        for (int q = 0; q < 4; q++) o_[bn][q] = 0.f;

    const float inv_hs = 1.f / 64.f;

    for (int kt = kt_beg; kt < kt_end; kt++) {
        const int k0 = kt * 64;
        __syncthreads();
#pragma unroll
        for (int s = 0; s < 8; s++) {
            int idx = tid + 128 * s;
            int r = idx >> 4, c4 = idx & 15;
            float4 kv = *(const float4*)&Kg[(size_t)(k0 + r) * HD + c4 * 4];
            *(float4*)&Ks[r * QSTR + c4 * 4] =
                make_float4(cvt_tf32(kv.x), cvt_tf32(kv.y), cvt_tf32(kv.z), cvt_tf32(kv.w));
            float4 vv = *(const float4*)&Vg[(size_t)(k0 + r) * HD + c4 * 4];
            *(float4*)&Vs[r * VSTR + c4 * 4] =
                make_float4(cvt_tf32(vv.x), cvt_tf32(vv.y), cvt_tf32(vv.z), cvt_tf32(vv.w));
        }
        __syncthreads();

        float sa[8][4];
#pragma unroll
        for (int bn = 0; bn < 8; bn++)
#pragma unroll
            for (int q = 0; q < 4; q++) sa[bn][q] = 0.f;
#pragma unroll
        for (int ks = 0; ks < 8; ks++) {
#pragma unroll
            for (int bn = 0; bn < 8; bn++) {
                uint32_t b0 = Ku[(bn * 8 + g) * QSTR + ks * 8 + t];
                uint32_t b1 = Ku[(bn * 8 + g) * QSTR + ks * 8 + t + 4];
                mma_m16n8k8(sa[bn], aQ[ks][0], aQ[ks][1], aQ[ks][2], aQ[ks][3], b0, b1);
            }
        }

        const bool diag = (kt == qt);
#pragma unroll
        for (int bn = 0; bn < 8; bn++)
#pragma unroll
            for (int q = 0; q < 4; q++) {
                float v = sa[bn][q] * inv_hs;
                if (diag) {
                    int col = k0 + bn * 8 + 2 * t + (q & 1);
                    int row = q0 + qb + g + ((q >= 2) ? 8 : 0);
                    if (col > row) v = -1e30f;
                }
                sa[bn][q] = v;
            }

        float mt0 = -1e30f, mt1 = -1e30f;
#pragma unroll
        for (int bn = 0; bn < 8; bn++) {
            mt0 = fmaxf(mt0, fmaxf(sa[bn][0], sa[bn][1]));
            mt1 = fmaxf(mt1, fmaxf(sa[bn][2], sa[bn][3]));
        }
#pragma unroll
        for (int off = 1; off <= 2; off <<= 1) {
            mt0 = fmaxf(mt0, __shfl_xor_sync(0xffffffffu, mt0, off));
            mt1 = fmaxf(mt1, __shfl_xor_sync(0xffffffffu, mt1, off));
        }
        float mn0 = fmaxf(m0v, mt0), mn1 = fmaxf(m1v, mt1);
        float c0 = __expf(m0v - mn0), c1 = __expf(m1v - mn1);

        float lt0 = 0.f, lt1 = 0.f;
#pragma unroll
        for (int bn = 0; bn < 8; bn++) {
            float p0 = __expf(sa[bn][0] - mn0);
            float p1 = __expf(sa[bn][1] - mn0);
            float p2 = __expf(sa[bn][2] - mn1);
            float p3 = __expf(sa[bn][3] - mn1);
            lt0 += p0 + p1;  lt1 += p2 + p3;
            *(float2*)&QP[(qb + g) * QSTR + bn * 8 + 2 * t] =
                make_float2(cvt_tf32(p0), cvt_tf32(p1));
            *(float2*)&QP[(qb + g + 8) * QSTR + bn * 8 + 2 * t] =
                make_float2(cvt_tf32(p2), cvt_tf32(p3));
            o_[bn][0] *= c0; o_[bn][1] *= c0; o_[bn][2] *= c1; o_[bn][3] *= c1;
        }
#pragma unroll
        for (int off = 1; off <= 2; off <<= 1) {
            lt0 += __shfl_xor_sync(0xffffffffu, lt0, off);
            lt1 += __shfl_xor_sync(0xffffffffu, lt1, off);
        }
        l0 = l0 * c0 + lt0;  l1 = l1 * c1 + lt1;
        m0v = mn0;  m1v = mn1;
        __syncwarp();

#pragma unroll
        for (int ks = 0; ks < 8; ks++) {
            uint32_t a0 = QPu[(qb + g) * QSTR + ks * 8 + t];
            uint32_t a1 = QPu[(qb + g + 8) * QSTR + ks * 8 + t];
            uint32_t a2 = QPu[(qb + g) * QSTR + ks * 8 + t + 4];
            uint32_t a3 = QPu[(qb + g + 8) * QSTR + ks * 8 + t + 4];
#pragma unroll
            for (int bn = 0; bn < 8; bn++) {
                uint32_t b0 = Vu[(ks * 8 + t) * VSTR + bn * 8 + g];
                uint32_t b1 = Vu[(ks * 8 + t + 4) * VSTR + bn * 8 + g];
                mma_m16n8k8(o_[bn], a0, a1, a2, a3, b0, b1);
            }
        }
        __syncwarp();
    }

    const int r0g = b * SEQ + q0 + qb + g;
    if (t == 0) {
        g_pm[half][r0g]     = m0v;  g_pl[half][r0g]     = l0;
        g_pm[half][r0g + 8] = m1v;  g_pl[half][r0g + 8] = l1;
    }
#pragma unroll
    for (int bn = 0; bn < 8; bn++) {
        int c = bn * 8 + 2 * t;
        *(float2*)&g_po[half][(size_t)r0g * HD + c] =
            make_float2(o_[bn][0], o_[bn][1]);
        *(float2*)&g_po[half][(size_t)(r0g + 8) * HD + c] =
            make_float2(o_[bn][2], o_[bn][3]);
    }
}

// ============================================================================
__global__ __launch_bounds__(256) void merge_kernel(float* __restrict__ out)
{
    int gid = blockIdx.x * 256 + threadIdx.x;
    int row = gid >> 4;
    int c   = (gid & 15) * 4;
    float m0 = g_pm[0][row], m1 = g_pm[1][row];
    float l0 = g_pl[0][row], l1 = g_pl[1][row];
    float M  = fmaxf(m0, m1);
    float w0 = __expf(m0 - M), w1 = __expf(m1 - M);
    float inv = 1.f / (l0 * w0 + l1 * w1);
    float4 a = *(const float4*)&g_po[0][(size_t)row * HD + c];
    float4 b = *(const float4*)&g_po[1][(size_t)row * HD + c];
    float4 r;
    r.x = (a.x * w0 + b.x * w1) * inv;
    r.y = (a.y * w0 + b.y * w1) * inv;
    r.z = (a.z * w0 + b.z * w1) * inv;
    r.w = (a.w * w0 + b.w * w1) * inv;
    *(float4*)&out[(size_t)row * HD + c] = r;
}

// ============================================================================
extern "C" void kernel_launch(void* const* d_in, const int* in_sizes, int n_in,
                              void* d_out, int out_size)
{
    const float* x  = (const float*)d_in[0];
    const float* Wq = (const float*)d_in[1];
    const float* Wk = (const float*)d_in[2];
    const float* Wv = (const float*)d_in[3];
    float* out = (float*)d_out;

    wcvt_kernel<<<3 * (EMB * HD / 4) / 256, 256>>>(Wq, Wk, Wv);
    proj_kernel<<<3 * NROWS / 64, 256>>>(x);

    cudaFuncSetAttribute(attn_kernel, cudaFuncAttributeMaxDynamicSharedMemorySize,
                         SM_TOT * sizeof(float));
    attn_kernel<<<512, 128, SM_TOT * sizeof(float)>>>();

    merge_kernel<<<NROWS * 16 / 256, 256>>>(out);
}

// round 6
// speedup vs baseline: 5.8568x; 1.8117x over previous
#include <cuda_runtime.h>
#include <cuda_fp16.h>
#include <math.h>
#include <stdint.h>

#define BATCH 8
#define SEQ   2048
#define EMB   1024
#define HD    64
#define NROWS (BATCH*SEQ)   // 16384

__device__ __half g_q[NROWS*HD];
__device__ __half g_k[NROWS*HD];
__device__ __half g_v[NROWS*HD];
__device__ __half g_wt[3][HD*EMB];   // [o][n][k] transposed fp16
// flash-decoding partials
__device__ float g_po[2][NROWS*HD];
__device__ float g_pm[2][NROWS];
__device__ float g_pl[2][NROWS];

// ---------------------------------------------------------------------------
__device__ __forceinline__ void mma_f16(float d[4],
                                        uint32_t a0, uint32_t a1, uint32_t a2, uint32_t a3,
                                        uint32_t b0, uint32_t b1) {
    asm volatile(
        "mma.sync.aligned.m16n8k16.row.col.f32.f16.f16.f32 "
        "{%0,%1,%2,%3},{%4,%5,%6,%7},{%8,%9},{%0,%1,%2,%3};\n"
        : "+f"(d[0]), "+f"(d[1]), "+f"(d[2]), "+f"(d[3])
        : "r"(a0), "r"(a1), "r"(a2), "r"(a3), "r"(b0), "r"(b1));
}
__device__ __forceinline__ uint32_t pack_h2(float lo, float hi) {
    __half2 h = __floats2half2_rn(lo, hi);
    return *(uint32_t*)&h;
}
__device__ __forceinline__ void ldmatrix_x4_t(uint32_t r[4], uint32_t saddr) {
    asm volatile("ldmatrix.sync.aligned.m8n8.x4.trans.shared.b16 {%0,%1,%2,%3}, [%4];"
                 : "=r"(r[0]), "=r"(r[1]), "=r"(r[2]), "=r"(r[3]) : "r"(saddr));
}

// ============================================================================
// W -> fp16, transposed to [n][k]
// ============================================================================
__global__ __launch_bounds__(256) void wtrans_kernel(
    const float* __restrict__ Wq, const float* __restrict__ Wk,
    const float* __restrict__ Wv)
{
    __shared__ float Ts[64][65];
    const float* src = (blockIdx.y == 0) ? Wq : (blockIdx.y == 1) ? Wk : Wv;
    const int k0 = blockIdx.x * 64;
    const int tid = threadIdx.x;
#pragma unroll
    for (int s = 0; s < 16; s++) {
        int e = tid + 256 * s;
        int kk = e >> 6, n = e & 63;
        Ts[kk][n] = src[(size_t)(k0 + kk) * HD + n];
    }
    __syncthreads();
#pragma unroll
    for (int s = 0; s < 16; s++) {
        int e = tid + 256 * s;
        int n = e >> 6, kk = e & 63;
        g_wt[blockIdx.y][(size_t)n * EMB + k0 + kk] = __float2half(Ts[kk][n]);
    }
}

// ============================================================================
// Fused projection, fp16 mma m16n8k16. BM=128? -> BM=64? : BM=64, 3 outs.
// grid 256, block 256 (8 warps: 2m x 4n). BK=64 (32 half2-words, stride 36).
// Double-buffered smem with register-prefetch LDG overlap.
// ============================================================================
#define PSTR 36
#define PROJ_SMEM ((2*64*PSTR + 3*2*64*PSTR) * 4)

__global__ __launch_bounds__(256, 2) void proj_kernel(const float* __restrict__ x)
{
    extern __shared__ uint32_t psm[];
    uint32_t* As = psm;                    // [buf][64*PSTR]
    uint32_t* Bs = psm + 2 * 64 * PSTR;    // [o][buf][64*PSTR]

    const int m0   = blockIdx.x * 64;
    const int tid  = threadIdx.x;
    const int w    = tid >> 5;
    const int lane = tid & 31;
    const int g    = lane >> 2;
    const int t    = lane & 3;
    const int wm   = w >> 2;      // 0..1 -> 32 rows
    const int wn   = w & 3;       // 0..3 -> 16 cols

    float acc[3][2][2][4];
#pragma unroll
    for (int o = 0; o < 3; o++)
#pragma unroll
        for (int i = 0; i < 2; i++)
#pragma unroll
            for (int j = 0; j < 2; j++)
#pragma unroll
                for (int q = 0; q < 4; q++) acc[o][i][j][q] = 0.f;

    // prefetch registers: A 2 units (8 fp32 each), B 3 units (uint4 of halves)
    float4 pa[2][2];
    uint4  pb[3];

    auto ldg_iter = [&](int k0c) {
#pragma unroll
        for (int s = 0; s < 2; s++) {
            int idx = tid + 256 * s;
            int r = idx >> 3, c = idx & 7;
            const float* src = &x[(size_t)(m0 + r) * EMB + k0c + c * 8];
            pa[s][0] = *(const float4*)src;
            pa[s][1] = *(const float4*)(src + 4);
        }
#pragma unroll
        for (int o = 0; o < 3; o++) {
            int idx = tid;                      // 256 of 512 units: 2 per thread
            int r = idx >> 3, c = idx & 7;
            pb[o] = *(const uint4*)&g_wt[o][(size_t)r * EMB + k0c + c * 8];
        }
    };
    // second half of B units handled below (512 units / 256 thr = 2); redo map:
    uint4 pb2[3];
    auto ldg_iter_b2 = [&](int k0c) {
#pragma unroll
        for (int o = 0; o < 3; o++) {
            int idx = tid + 256;
            int r = idx >> 3, c = idx & 7;
            pb2[o] = *(const uint4*)&g_wt[o][(size_t)r * EMB + k0c + c * 8];
        }
    };

    auto sts_iter = [&](int buf) {
#pragma unroll
        for (int s = 0; s < 2; s++) {
            int idx = tid + 256 * s;
            int r = idx >> 3, c = idx & 7;
            uint4 v;
            v.x = pack_h2(pa[s][0].x, pa[s][0].y);
            v.y = pack_h2(pa[s][0].z, pa[s][0].w);
            v.z = pack_h2(pa[s][1].x, pa[s][1].y);
            v.w = pack_h2(pa[s][1].z, pa[s][1].w);
            *(uint4*)&As[buf * 64 * PSTR + r * PSTR + c * 4] = v;
        }
#pragma unroll
        for (int o = 0; o < 3; o++) {
            {
                int idx = tid;
                int r = idx >> 3, c = idx & 7;
                *(uint4*)&Bs[(o * 2 + buf) * 64 * PSTR + r * PSTR + c * 4] = pb[o];
            }
            {
                int idx = tid + 256;
                int r = idx >> 3, c = idx & 7;
                *(uint4*)&Bs[(o * 2 + buf) * 64 * PSTR + r * PSTR + c * 4] = pb2[o];
            }
        }
    };

    ldg_iter(0);
    ldg_iter_b2(0);

    for (int it = 0; it < 16; it++) {
        const int buf = it & 1;
        sts_iter(buf);
        __syncthreads();
        if (it + 1 < 16) { ldg_iter((it + 1) * 64); ldg_iter_b2((it + 1) * 64); }

        const uint32_t* Ab = As + buf * 64 * PSTR;
#pragma unroll
        for (int ks = 0; ks < 4; ks++) {
            uint32_t a[2][4];
#pragma unroll
            for (int am = 0; am < 2; am++) {
                int rb = wm * 32 + am * 16;
                a[am][0] = Ab[(rb + g) * PSTR + ks * 8 + t];
                a[am][1] = Ab[(rb + g + 8) * PSTR + ks * 8 + t];
                a[am][2] = Ab[(rb + g) * PSTR + ks * 8 + t + 4];
                a[am][3] = Ab[(rb + g + 8) * PSTR + ks * 8 + t + 4];
            }
#pragma unroll
            for (int o = 0; o < 3; o++) {
                const uint32_t* Bb = Bs + (o * 2 + buf) * 64 * PSTR;
#pragma unroll
                for (int bn = 0; bn < 2; bn++) {
                    int nb = wn * 16 + bn * 8;
                    uint32_t b0 = Bb[(nb + g) * PSTR + ks * 8 + t];
                    uint32_t b1 = Bb[(nb + g) * PSTR + ks * 8 + t + 4];
#pragma unroll
                    for (int am = 0; am < 2; am++)
                        mma_f16(acc[o][am][bn], a[am][0], a[am][1], a[am][2], a[am][3], b0, b1);
                }
            }
        }
        __syncthreads();
    }

    __half* outs[3] = {g_q, g_k, g_v};
#pragma unroll
    for (int o = 0; o < 3; o++)
#pragma unroll
        for (int am = 0; am < 2; am++)
#pragma unroll
            for (int bn = 0; bn < 2; bn++) {
                int r0 = m0 + wm * 32 + am * 16 + g;
                int c  = wn * 16 + bn * 8 + 2 * t;
                *(__half2*)&outs[o][(size_t)r0 * HD + c] =
                    __floats2half2_rn(acc[o][am][bn][0], acc[o][am][bn][1]);
                *(__half2*)&outs[o][(size_t)(r0 + 8) * HD + c] =
                    __floats2half2_rn(acc[o][am][bn][2], acc[o][am][bn][3]);
            }
}

// ============================================================================
// Flash attention, fp16 mma, P register-resident, V via ldmatrix.trans.
// grid 512 (qt heavy-first x batch x kv-half), 128 thr / 4 warps.
// ============================================================================
#define QSTR 36   // words (half2) per row

__global__ __launch_bounds__(128, 4) void attn_kernel()
{
    __shared__ uint32_t Qs[64 * QSTR];
    __shared__ uint32_t Ks[64 * QSTR];
    __shared__ uint32_t Vs[64 * QSTR];

    const int bx   = blockIdx.x;
    const int qt   = 31 - (bx >> 4);
    const int sub  = bx & 15;
    const int b    = sub >> 1;
    const int half = sub & 1;
    const int q0   = qt * 64;

    const int nk     = qt + 1;
    const int nhalf  = (nk + 1) >> 1;
    const int kt_beg = half ? nhalf : 0;
    const int kt_end = half ? nk : nhalf;

    const __half* Qg = g_q + (size_t)b * SEQ * HD;
    const __half* Kg = g_k + (size_t)b * SEQ * HD;
    const __half* Vg = g_v + (size_t)b * SEQ * HD;

    const int tid  = threadIdx.x;
    const int lane = tid & 31;
    const int w    = tid >> 5;
    const int g    = lane >> 2;
    const int t    = lane & 3;
    const int qb   = w * 16;

    // stage Q: 64 rows x 8 f4-chunks (8 halves) = 512 units, 4/thread
#pragma unroll
    for (int s = 0; s < 4; s++) {
        int idx = tid + 128 * s;
        int r = idx >> 3, c = idx & 7;
        *(uint4*)&Qs[r * QSTR + c * 4] = *(const uint4*)&Qg[(size_t)(q0 + r) * HD + c * 8];
    }
    __syncthreads();

    uint32_t aQ[4][4];
#pragma unroll
    for (int ks = 0; ks < 4; ks++) {
        aQ[ks][0] = Qs[(qb + g) * QSTR + ks * 8 + t];
        aQ[ks][1] = Qs[(qb + g + 8) * QSTR + ks * 8 + t];
        aQ[ks][2] = Qs[(qb + g) * QSTR + ks * 8 + t + 4];
        aQ[ks][3] = Qs[(qb + g + 8) * QSTR + ks * 8 + t + 4];
    }

    float o_[8][4];
    float m0v = -1e30f, m1v = -1e30f, l0 = 0.f, l1 = 0.f;
#pragma unroll
    for (int bn = 0; bn < 8; bn++)
#pragma unroll
        for (int q = 0; q < 4; q++) o_[bn][q] = 0.f;

    const float inv_hs = 1.f / 64.f;
    const uint32_t Vs_u = (uint32_t)__cvta_generic_to_shared(Vs);
    const uint32_t vrow_off = ((lane & 15) * QSTR + (lane >> 4) * 4) * 4;  // bytes

    for (int kt = kt_beg; kt < kt_end; kt++) {
        const int k0 = kt * 64;
        __syncthreads();
#pragma unroll
        for (int s = 0; s < 4; s++) {
            int idx = tid + 128 * s;
            int r = idx >> 3, c = idx & 7;
            *(uint4*)&Ks[r * QSTR + c * 4] = *(const uint4*)&Kg[(size_t)(k0 + r) * HD + c * 8];
            *(uint4*)&Vs[r * QSTR + c * 4] = *(const uint4*)&Vg[(size_t)(k0 + r) * HD + c * 8];
        }
        __syncthreads();

        // S = Q @ K^T (fp16, k=64 in 4 chunks)
        float sa[8][4];
#pragma unroll
        for (int bn = 0; bn < 8; bn++)
#pragma unroll
            for (int q = 0; q < 4; q++) sa[bn][q] = 0.f;
#pragma unroll
        for (int ks = 0; ks < 4; ks++) {
#pragma unroll
            for (int bn = 0; bn < 8; bn++) {
                uint32_t b0 = Ks[(bn * 8 + g) * QSTR + ks * 8 + t];
                uint32_t b1 = Ks[(bn * 8 + g) * QSTR + ks * 8 + t + 4];
                mma_f16(sa[bn], aQ[ks][0], aQ[ks][1], aQ[ks][2], aQ[ks][3], b0, b1);
            }
        }

        const bool diag = (kt == qt);
#pragma unroll
        for (int bn = 0; bn < 8; bn++)
#pragma unroll
            for (int q = 0; q < 4; q++) {
                float v = sa[bn][q] * inv_hs;
                if (diag) {
                    int col = k0 + bn * 8 + 2 * t + (q & 1);
                    int row = q0 + qb + g + ((q >= 2) ? 8 : 0);
                    if (col > row) v = -1e30f;
                }
                sa[bn][q] = v;
            }

        float mt0 = -1e30f, mt1 = -1e30f;
#pragma unroll
        for (int bn = 0; bn < 8; bn++) {
            mt0 = fmaxf(mt0, fmaxf(sa[bn][0], sa[bn][1]));
            mt1 = fmaxf(mt1, fmaxf(sa[bn][2], sa[bn][3]));
        }
#pragma unroll
        for (int off = 1; off <= 2; off <<= 1) {
            mt0 = fmaxf(mt0, __shfl_xor_sync(0xffffffffu, mt0, off));
            mt1 = fmaxf(mt1, __shfl_xor_sync(0xffffffffu, mt1, off));
        }
        float mn0 = fmaxf(m0v, mt0), mn1 = fmaxf(m1v, mt1);
        float c0 = __expf(m0v - mn0), c1 = __expf(m1v - mn1);

        // P = exp(S - m): pack straight into PV A-fragments (no smem!)
        uint32_t pA[4][4];
        float lt0 = 0.f, lt1 = 0.f;
#pragma unroll
        for (int bn = 0; bn < 8; bn++) {
            float p0 = __expf(sa[bn][0] - mn0);
            float p1 = __expf(sa[bn][1] - mn0);
            float p2 = __expf(sa[bn][2] - mn1);
            float p3 = __expf(sa[bn][3] - mn1);
            lt0 += p0 + p1;  lt1 += p2 + p3;
            int ks = bn >> 1;
            if ((bn & 1) == 0) {
                pA[ks][0] = pack_h2(p0, p1);
                pA[ks][1] = pack_h2(p2, p3);
            } else {
                pA[ks][2] = pack_h2(p0, p1);
                pA[ks][3] = pack_h2(p2, p3);
            }
            o_[bn][0] *= c0; o_[bn][1] *= c0; o_[bn][2] *= c1; o_[bn][3] *= c1;
        }
#pragma unroll
        for (int off = 1; off <= 2; off <<= 1) {
            lt0 += __shfl_xor_sync(0xffffffffu, lt0, off);
            lt1 += __shfl_xor_sync(0xffffffffu, lt1, off);
        }
        l0 = l0 * c0 + lt0;  l1 = l1 * c1 + lt1;
        m0v = mn0;  m1v = mn1;

        // O += P @ V, V fragments via ldmatrix.x4.trans (2 h-col groups each)
#pragma unroll
        for (int ks = 0; ks < 4; ks++) {
#pragma unroll
            for (int bnp = 0; bnp < 4; bnp++) {
                uint32_t vb[4];
                ldmatrix_x4_t(vb, Vs_u + (ks * 16 * QSTR + bnp * 8) * 4 + vrow_off);
                mma_f16(o_[2 * bnp],     pA[ks][0], pA[ks][1], pA[ks][2], pA[ks][3], vb[0], vb[1]);
                mma_f16(o_[2 * bnp + 1], pA[ks][0], pA[ks][1], pA[ks][2], pA[ks][3], vb[2], vb[3]);
            }
        }
    }

    // write unnormalized partials (fp32)
    const int r0g = b * SEQ + q0 + qb + g;
    if (t == 0) {
        g_pm[half][r0g]     = m0v;  g_pl[half][r0g]     = l0;
        g_pm[half][r0g + 8] = m1v;  g_pl[half][r0g + 8] = l1;
    }
#pragma unroll
    for (int bn = 0; bn < 8; bn++) {
        int c = bn * 8 + 2 * t;
        *(float2*)&g_po[half][(size_t)r0g * HD + c] = make_float2(o_[bn][0], o_[bn][1]);
        *(float2*)&g_po[half][(size_t)(r0g + 8) * HD + c] = make_float2(o_[bn][2], o_[bn][3]);
    }
}

// ============================================================================
__global__ __launch_bounds__(256) void merge_kernel(float* __restrict__ out)
{
    int gid = blockIdx.x * 256 + threadIdx.x;
    int row = gid >> 4;
    int c   = (gid & 15) * 4;
    float m0 = g_pm[0][row], m1 = g_pm[1][row];
    float l0 = g_pl[0][row], l1 = g_pl[1][row];
    float M  = fmaxf(m0, m1);
    float w0 = __expf(m0 - M), w1 = __expf(m1 - M);
    float inv = 1.f / (l0 * w0 + l1 * w1);
    float4 a = *(const float4*)&g_po[0][(size_t)row * HD + c];
    float4 b = *(const float4*)&g_po[1][(size_t)row * HD + c];
    float4 r;
    r.x = (a.x * w0 + b.x * w1) * inv;
    r.y = (a.y * w0 + b.y * w1) * inv;
    r.z = (a.z * w0 + b.z * w1) * inv;
    r.w = (a.w * w0 + b.w * w1) * inv;
    *(float4*)&out[(size_t)row * HD + c] = r;
}

// ============================================================================
extern "C" void kernel_launch(void* const* d_in, const int* in_sizes, int n_in,
                              void* d_out, int out_size)
{
    const float* x  = (const float*)d_in[0];
    const float* Wq = (const float*)d_in[1];
    const float* Wk = (const float*)d_in[2];
    const float* Wv = (const float*)d_in[3];
    float* out = (float*)d_out;

    wtrans_kernel<<<dim3(16, 3), 256>>>(Wq, Wk, Wv);

    cudaFuncSetAttribute(proj_kernel, cudaFuncAttributeMaxDynamicSharedMemorySize,
                         PROJ_SMEM);
    proj_kernel<<<NROWS / 64, 256, PROJ_SMEM>>>(x);

    attn_kernel<<<512, 128>>>();

    merge_kernel<<<NROWS * 16 / 256, 256>>>(out);
}